// round 9
// baseline (speedup 1.0000x reference)
#include <cuda_runtime.h>
#include <cuda_fp16.h>
#include <math.h>

#define NB    64
#define NI    2048
#define KA    8
#define NO    32
#define OA    16
#define OUT   512

#define BGRP  32              // batch elements per group (votes/group = 64 MB, L2-resident)
#define NGRP  (NB / BGRP)     // 2

__device__ float g_S[NB * OUT];        // cumulative sum of activations
__device__ float g_preact[NB * OUT];
// votes fp16, SoA-chunked: uint2 (4 halves = atoms 4c..4c+3 of capsule j=lane)
// index: ((b*NI + i)*4 + c)*32 + lane          -> 128 MB
__device__ uint2 g_votes[(size_t)NB * NI * 4 * 32];

typedef unsigned long long u64;

// ---- f32x2 helpers ----
__device__ __forceinline__ u64 fma2(u64 a, u64 b, u64 c) {
    u64 d; asm("fma.rn.f32x2 %0, %1, %2, %3;" : "=l"(d) : "l"(a), "l"(b), "l"(c)); return d;
}
__device__ __forceinline__ u64 pack2(float lo, float hi) {
    u64 d; asm("mov.b64 %0, {%1, %2};" : "=l"(d) : "f"(lo), "f"(hi)); return d;
}
__device__ __forceinline__ void unpack2(u64 v, float& lo, float& hi) {
    asm("mov.b64 {%0, %1}, %2;" : "=f"(lo), "=f"(hi) : "l"(v));
}
__device__ __forceinline__ void cp16(void* smem_dst, const void* gsrc) {
    unsigned s = (unsigned)__cvta_generic_to_shared(smem_dst);
    asm volatile("cp.async.cg.shared.global [%0], [%1], 16;" :: "r"(s), "l"(gsrc));
}
__device__ __forceinline__ int swz(int b) { return b ^ ((b >> 3) & 0x70); }

// ---------------------------------------------------------------- zero
__global__ void k_zero() {
    int t = blockIdx.x * blockDim.x + threadIdx.x;
    if (t < NB * OUT) { g_S[t] = 0.0f; g_preact[t] = 0.0f; }
}

// ---------------------------------------------------------------- gen + pass0 (one b-group)
// grid = (NI/ITA = 128, 1), block 256 (8 warps). lane = j; warp owns 4 b.
// One block covers all 32 b of the group for its i-tile -> W read once per group.
// W[i] staged in smem (cp.async dbl buffer). Stores fp16 votes (uint2, coalesced)
// and accumulates pass-0 preact (route = 1/33).
#define ITA 16
__global__ void __launch_bounds__(256, 1)
k_gen(const float* __restrict__ x, const float* __restrict__ W, int group) {
    __shared__ char ws[2 * KA * OUT * 4];     // 32 KB dbl-buffered W tile

    const int tid  = threadIdx.x;
    const int w    = tid >> 5;
    const int lane = tid & 31;
    const int it0  = blockIdx.x * ITA;
    const int b0   = group * BGRP + w * 4;

    {   // prefetch first tile (16 KB = 1024 float4, 4 per thread)
        const float4* g = (const float4*)(W + (size_t)it0 * KA * OUT);
#pragma unroll
        for (int r = 0; r < 4; r++) { int f4 = tid + 256 * r; cp16(ws + swz(f4 * 16), &g[f4]); }
        asm volatile("cp.async.commit_group;" ::: "memory");
    }

    u64 acc[4][8];
#pragma unroll
    for (int bq = 0; bq < 4; bq++)
#pragma unroll
        for (int p = 0; p < 8; p++) acc[bq][p] = 0ull;
    const u64 c33 = pack2(1.0f / 33.0f, 1.0f / 33.0f);

    for (int ii = 0; ii < ITA; ii++) {
        asm volatile("cp.async.wait_group 0;" ::: "memory");
        __syncthreads();

        if (ii + 1 < ITA) {
            const float4* g = (const float4*)(W + (size_t)(it0 + ii + 1) * KA * OUT);
            char* dst = ws + ((ii + 1) & 1) * (KA * OUT * 4);
#pragma unroll
            for (int r = 0; r < 4; r++) { int f4 = tid + 256 * r; cp16(dst + swz(f4 * 16), &g[f4]); }
            asm volatile("cp.async.commit_group;" ::: "memory");
        }

        const char* Wc = ws + (ii & 1) * (KA * OUT * 4);
        const int i = it0 + ii;

        float xk[4][KA];
#pragma unroll
        for (int bq = 0; bq < 4; bq++) {
            const float4* xp = (const float4*)&x[((size_t)(b0 + bq) * NI + i) * KA];
            float4 x0 = __ldg(xp), x1 = __ldg(xp + 1);
            xk[bq][0]=x0.x; xk[bq][1]=x0.y; xk[bq][2]=x0.z; xk[bq][3]=x0.w;
            xk[bq][4]=x1.x; xk[bq][5]=x1.y; xk[bq][6]=x1.z; xk[bq][7]=x1.w;
        }

        u64 v[4][8];
#pragma unroll
        for (int bq = 0; bq < 4; bq++)
#pragma unroll
            for (int p = 0; p < 8; p++) v[bq][p] = 0ull;

#pragma unroll
        for (int k = 0; k < KA; k++) {
            u64 xb[4];
#pragma unroll
            for (int bq = 0; bq < 4; bq++) xb[bq] = pack2(xk[bq][k], xk[bq][k]);
#pragma unroll
            for (int q = 0; q < 4; q++) {
                ulonglong2 wv = *(const ulonglong2*)(Wc + swz(k * 2048 + lane * 64 + q * 16));
#pragma unroll
                for (int bq = 0; bq < 4; bq++) {
                    v[bq][2*q]   = fma2(xb[bq], wv.x, v[bq][2*q]);
                    v[bq][2*q+1] = fma2(xb[bq], wv.y, v[bq][2*q+1]);
                }
            }
        }

#pragma unroll
        for (int bq = 0; bq < 4; bq++) {
            unsigned h[8];
#pragma unroll
            for (int p = 0; p < 8; p++) {
                acc[bq][p] = fma2(c33, v[bq][p], acc[bq][p]);
                float f0, f1; unpack2(v[bq][p], f0, f1);
                __half2 hh = __floats2half2_rn(f0, f1);
                h[p] = *(unsigned*)&hh;
            }
            uint2* dst = &g_votes[(((size_t)(b0 + bq) * NI + i) * 4) * 32 + lane];
#pragma unroll
            for (int c = 0; c < 4; c++)
                dst[c * 32] = make_uint2(h[2*c], h[2*c+1]);
        }
    }

#pragma unroll
    for (int bq = 0; bq < 4; bq++) {
        float* dst = &g_preact[(size_t)(b0 + bq) * OUT + lane * OA];
#pragma unroll
        for (int p = 0; p < 8; p++) {
            float a0, a1; unpack2(acc[bq][p], a0, a1);
            atomicAdd(dst + 2*p, a0);
            atomicAdd(dst + 2*p + 1, a1);
        }
    }
}

// ---------------------------------------------------------------- route pass (one b-group)
// grid = (16, BGRP), block 256 (8 warps). warp = 16-i chunk of batch b; lane = j.
// Exact R4 inner loop (unroll-4, 4x LDG.64 per i); votes reads hit L2 (group-resident).
#define IW 16
__global__ void __launch_bounds__(256)
k_pass(int group) {
    const int tid  = threadIdx.x;
    const int w    = tid >> 5;
    const int lane = tid & 31;
    const int b    = group * BGRP + blockIdx.y;
    const int i0   = (blockIdx.x * 8 + w) * IW;

    // S[b, lane*16 .. +16) in 8 u64 regs
    u64 s[8];
    {
        const ulonglong2* sp = (const ulonglong2*)&g_S[(size_t)b * OUT + lane * OA];
#pragma unroll
        for (int q = 0; q < 4; q++) { ulonglong2 t = __ldg(sp + q); s[2*q] = t.x; s[2*q+1] = t.y; }
    }

    u64 acc[8];
#pragma unroll
    for (int p = 0; p < 8; p++) acc[p] = 0ull;

    const uint2* src = &g_votes[(((size_t)b * NI + i0) * 4) * 32 + lane];

#pragma unroll 4
    for (int m = 0; m < IW; m++) {
        uint2 u[4];
#pragma unroll
        for (int c = 0; c < 4; c++) u[c] = __ldg(src + (size_t)m * 128 + c * 32);

        u64 v[8];
#pragma unroll
        for (int c = 0; c < 4; c++) {
            float2 f0 = __half22float2(*(__half2*)&u[c].x);
            float2 f1 = __half22float2(*(__half2*)&u[c].y);
            v[2*c]   = pack2(f0.x, f0.y);
            v[2*c+1] = pack2(f1.x, f1.y);
        }

        u64 l2 = 0ull;
#pragma unroll
        for (int p = 0; p < 8; p++) l2 = fma2(v[p], s[p], l2);
        float a0, a1; unpack2(l2, a0, a1);
        float e = __expf(a0 + a1);

        float tot = e;
#pragma unroll
        for (int d = 16; d > 0; d >>= 1)
            tot += __shfl_xor_sync(0xFFFFFFFFu, tot, d);
        float r = __fdividef(e, 1.0f + tot);       // leaky softmax (leak logit 0)

        u64 r2 = pack2(r, r);
#pragma unroll
        for (int p = 0; p < 8; p++) acc[p] = fma2(r2, v[p], acc[p]);
    }

    float* dst = &g_preact[(size_t)b * OUT + lane * OA];
#pragma unroll
    for (int p = 0; p < 8; p++) {
        float a0, a1; unpack2(acc[p], a0, a1);
        atomicAdd(dst + 2*p, a0);
        atomicAdd(dst + 2*p + 1, a1);
    }
}

// ---------------------------------------------------------------- squash (one b-group)
__global__ void k_squash(const float* __restrict__ bias, float* __restrict__ out, int group) {
    const int b = group * BGRP + blockIdx.x;
    const int t = threadIdx.x;

    float p = g_preact[b * OUT + t] + bias[t];
    float sq = p * p;
#pragma unroll
    for (int d = 1; d < OA; d <<= 1)
        sq += __shfl_xor_sync(0xFFFFFFFFu, sq, d);
    float nrm = sqrtf(sq);
    float scale = nrm / (1.0f + sq);
    float a = p * scale;

    out[b * OUT + t] = a;
    g_S[b * OUT + t] += a;
    g_preact[b * OUT + t] = 0.0f;
}

// ---------------------------------------------------------------- launch
extern "C" void kernel_launch(void* const* d_in, const int* in_sizes, int n_in,
                              void* d_out, int out_size) {
    const float* x    = (const float*)d_in[0];   // [64, 2048, 8]
    const float* W    = (const float*)d_in[1];   // [2048, 8, 512]
    const float* bias = (const float*)d_in[2];   // [32, 16]
    float* out = (float*)d_out;                  // [64, 32, 16]

    k_zero<<<64, 512>>>();
    for (int g = 0; g < NGRP; g++) {
        k_gen<<<dim3(NI / ITA, 1), 256>>>(x, W, g);    // votes + pass 0 for group g
        k_squash<<<BGRP, 512>>>(bias, out, g);
        k_pass<<<dim3(16, BGRP), 256>>>(g);            // pass 1 (L2-resident votes)
        k_squash<<<BGRP, 512>>>(bias, out, g);
        k_pass<<<dim3(16, BGRP), 256>>>(g);            // pass 2
        k_squash<<<BGRP, 512>>>(bias, out, g);
    }
}

// round 10
// speedup vs baseline: 1.9481x; 1.9481x over previous
#include <cuda_runtime.h>
#include <cuda_fp16.h>
#include <math.h>

#define NB    64
#define NI    2048
#define KA    8
#define NO    32
#define OA    16
#define OUT   512

#define NSLOT 64

__device__ float g_S[NB * OUT];                 // cumulative sum of activations
__device__ float g_part[NSLOT * NB * OUT];      // partial preact, slot-partitioned (8 MB)
// votes fp16, SoA-chunked: uint2 (4 halves = atoms 4c..4c+3 of capsule j=lane)
// index: ((b*NI + i)*4 + c)*32 + lane          -> 128 MB
__device__ uint2 g_votes[(size_t)NB * NI * 4 * 32];

typedef unsigned long long u64;

// ---- f32x2 helpers ----
__device__ __forceinline__ u64 fma2(u64 a, u64 b, u64 c) {
    u64 d; asm("fma.rn.f32x2 %0, %1, %2, %3;" : "=l"(d) : "l"(a), "l"(b), "l"(c)); return d;
}
__device__ __forceinline__ u64 pack2(float lo, float hi) {
    u64 d; asm("mov.b64 %0, {%1, %2};" : "=l"(d) : "f"(lo), "f"(hi)); return d;
}
__device__ __forceinline__ void unpack2(u64 v, float& lo, float& hi) {
    asm("mov.b64 {%0, %1}, %2;" : "=f"(lo), "=f"(hi) : "l"(v));
}
__device__ __forceinline__ void cp16(void* smem_dst, const void* gsrc) {
    unsigned s = (unsigned)__cvta_generic_to_shared(smem_dst);
    asm volatile("cp.async.cg.shared.global [%0], [%1], 16;" :: "r"(s), "l"(gsrc));
}
__device__ __forceinline__ int swz(int b) { return b ^ ((b >> 3) & 0x70); }

// ---------------------------------------------------------------- zero (S only)
__global__ void k_zero() {
    int t = blockIdx.x * blockDim.x + threadIdx.x;
    if (t < NB * OUT) g_S[t] = 0.0f;
}

// ---------------------------------------------------------------- gen + pass0
// grid = (NI/32 = 64, NB/32 = 2), block 256 (8 warps). lane = j; warp owns 4 b.
// W[i] staged in smem (cp.async dbl buffer). Stores fp16 votes (uint2, coalesced)
// and writes pass-0 partial preact (route = 1/33) to slot blockIdx.x. No atomics.
#define ITA 32
__global__ void __launch_bounds__(256, 1)
k_gen(const float* __restrict__ x, const float* __restrict__ W) {
    __shared__ char ws[2 * KA * OUT * 4];     // 32 KB dbl-buffered W tile

    const int tid  = threadIdx.x;
    const int w    = tid >> 5;
    const int lane = tid & 31;
    const int it0  = blockIdx.x * ITA;
    const int b0   = blockIdx.y * 32 + w * 4;

    {   // prefetch first tile (16 KB = 1024 float4, 4 per thread)
        const float4* g = (const float4*)(W + (size_t)it0 * KA * OUT);
#pragma unroll
        for (int r = 0; r < 4; r++) { int f4 = tid + 256 * r; cp16(ws + swz(f4 * 16), &g[f4]); }
        asm volatile("cp.async.commit_group;" ::: "memory");
    }

    u64 acc[4][8];
#pragma unroll
    for (int bq = 0; bq < 4; bq++)
#pragma unroll
        for (int p = 0; p < 8; p++) acc[bq][p] = 0ull;
    const u64 c33 = pack2(1.0f / 33.0f, 1.0f / 33.0f);

    for (int ii = 0; ii < ITA; ii++) {
        asm volatile("cp.async.wait_group 0;" ::: "memory");
        __syncthreads();

        if (ii + 1 < ITA) {
            const float4* g = (const float4*)(W + (size_t)(it0 + ii + 1) * KA * OUT);
            char* dst = ws + ((ii + 1) & 1) * (KA * OUT * 4);
#pragma unroll
            for (int r = 0; r < 4; r++) { int f4 = tid + 256 * r; cp16(dst + swz(f4 * 16), &g[f4]); }
            asm volatile("cp.async.commit_group;" ::: "memory");
        }

        const char* Wc = ws + (ii & 1) * (KA * OUT * 4);
        const int i = it0 + ii;

        float xk[4][KA];
#pragma unroll
        for (int bq = 0; bq < 4; bq++) {
            const float4* xp = (const float4*)&x[((size_t)(b0 + bq) * NI + i) * KA];
            float4 x0 = __ldg(xp), x1 = __ldg(xp + 1);
            xk[bq][0]=x0.x; xk[bq][1]=x0.y; xk[bq][2]=x0.z; xk[bq][3]=x0.w;
            xk[bq][4]=x1.x; xk[bq][5]=x1.y; xk[bq][6]=x1.z; xk[bq][7]=x1.w;
        }

        u64 v[4][8];
#pragma unroll
        for (int bq = 0; bq < 4; bq++)
#pragma unroll
            for (int p = 0; p < 8; p++) v[bq][p] = 0ull;

#pragma unroll
        for (int k = 0; k < KA; k++) {
            u64 xb[4];
#pragma unroll
            for (int bq = 0; bq < 4; bq++) xb[bq] = pack2(xk[bq][k], xk[bq][k]);
#pragma unroll
            for (int q = 0; q < 4; q++) {
                ulonglong2 wv = *(const ulonglong2*)(Wc + swz(k * 2048 + lane * 64 + q * 16));
#pragma unroll
                for (int bq = 0; bq < 4; bq++) {
                    v[bq][2*q]   = fma2(xb[bq], wv.x, v[bq][2*q]);
                    v[bq][2*q+1] = fma2(xb[bq], wv.y, v[bq][2*q+1]);
                }
            }
        }

#pragma unroll
        for (int bq = 0; bq < 4; bq++) {
            unsigned h[8];
#pragma unroll
            for (int p = 0; p < 8; p++) {
                acc[bq][p] = fma2(c33, v[bq][p], acc[bq][p]);
                float f0, f1; unpack2(v[bq][p], f0, f1);
                __half2 hh = __floats2half2_rn(f0, f1);
                h[p] = *(unsigned*)&hh;
            }
            uint2* dst = &g_votes[(((size_t)(b0 + bq) * NI + i) * 4) * 32 + lane];
#pragma unroll
            for (int c = 0; c < 4; c++)
                dst[c * 32] = make_uint2(h[2*c], h[2*c+1]);
        }
    }

    // slot-partitioned partial store (no atomics): slot = blockIdx.x
#pragma unroll
    for (int bq = 0; bq < 4; bq++) {
        float4* dst = (float4*)&g_part[((size_t)blockIdx.x * NB + (b0 + bq)) * OUT + lane * OA];
#pragma unroll
        for (int q = 0; q < 4; q++) {
            float a0, a1, a2, a3;
            unpack2(acc[bq][2*q],   a0, a1);
            unpack2(acc[bq][2*q+1], a2, a3);
            dst[q] = make_float4(a0, a1, a2, a3);
        }
    }
}

// ---------------------------------------------------------------- route pass
// grid = (8, 64): warp = (b = blockIdx.y, 32-i chunk), lane = j.  R4 inner loop
// (unroll-4, 4x LDG.64 per i). Partial preact -> slot blockIdx.x*8 + w. No atomics.
#define IW 32
__global__ void __launch_bounds__(256)
k_pass() {
    const int tid  = threadIdx.x;
    const int w    = tid >> 5;
    const int lane = tid & 31;
    const int b    = blockIdx.y;
    const int i0   = (blockIdx.x * 8 + w) * IW;

    // S[b, lane*16 .. +16) in 8 u64 regs
    u64 s[8];
    {
        const ulonglong2* sp = (const ulonglong2*)&g_S[(size_t)b * OUT + lane * OA];
#pragma unroll
        for (int q = 0; q < 4; q++) { ulonglong2 t = __ldg(sp + q); s[2*q] = t.x; s[2*q+1] = t.y; }
    }

    u64 acc[8];
#pragma unroll
    for (int p = 0; p < 8; p++) acc[p] = 0ull;

    const uint2* src = &g_votes[(((size_t)b * NI + i0) * 4) * 32 + lane];

#pragma unroll 4
    for (int m = 0; m < IW; m++) {
        uint2 u[4];
#pragma unroll
        for (int c = 0; c < 4; c++) u[c] = __ldg(src + (size_t)m * 128 + c * 32);

        u64 v[8];
#pragma unroll
        for (int c = 0; c < 4; c++) {
            float2 f0 = __half22float2(*(__half2*)&u[c].x);
            float2 f1 = __half22float2(*(__half2*)&u[c].y);
            v[2*c]   = pack2(f0.x, f0.y);
            v[2*c+1] = pack2(f1.x, f1.y);
        }

        u64 l2 = 0ull;
#pragma unroll
        for (int p = 0; p < 8; p++) l2 = fma2(v[p], s[p], l2);
        float a0, a1; unpack2(l2, a0, a1);
        float e = __expf(a0 + a1);

        float tot = e;
#pragma unroll
        for (int d = 16; d > 0; d >>= 1)
            tot += __shfl_xor_sync(0xFFFFFFFFu, tot, d);
        float r = __fdividef(e, 1.0f + tot);       // leaky softmax (leak logit 0)

        u64 r2 = pack2(r, r);
#pragma unroll
        for (int p = 0; p < 8; p++) acc[p] = fma2(r2, v[p], acc[p]);
    }

    // slot-partitioned partial store: slot = blockIdx.x*8 + w  (covers 0..63 per b)
    const int slot = blockIdx.x * 8 + w;
    float4* dst = (float4*)&g_part[((size_t)slot * NB + b) * OUT + lane * OA];
#pragma unroll
    for (int q = 0; q < 4; q++) {
        float a0, a1, a2, a3;
        unpack2(acc[2*q],   a0, a1);
        unpack2(acc[2*q+1], a2, a3);
        dst[q] = make_float4(a0, a1, a2, a3);
    }
}

// ---------------------------------------------------------------- squash
// grid = 64 (b), block = 512. Sums the 64 partial slots + bias, squashes,
// writes out and updates S.
__global__ void k_squash(const float* __restrict__ bias, float* __restrict__ out) {
    const int b = blockIdx.x;
    const int t = threadIdx.x;

    float p = bias[t];
    const float* base = &g_part[(size_t)b * OUT + t];
#pragma unroll 16
    for (int s = 0; s < NSLOT; s++)
        p += __ldg(base + (size_t)s * NB * OUT);

    float sq = p * p;
#pragma unroll
    for (int d = 1; d < OA; d <<= 1)
        sq += __shfl_xor_sync(0xFFFFFFFFu, sq, d);
    float nrm = sqrtf(sq);
    float scale = nrm / (1.0f + sq);
    float a = p * scale;

    out[b * OUT + t] = a;
    g_S[b * OUT + t] += a;
}

// ---------------------------------------------------------------- launch
extern "C" void kernel_launch(void* const* d_in, const int* in_sizes, int n_in,
                              void* d_out, int out_size) {
    const float* x    = (const float*)d_in[0];   // [64, 2048, 8]
    const float* W    = (const float*)d_in[1];   // [2048, 8, 512]
    const float* bias = (const float*)d_in[2];   // [32, 16]
    float* out = (float*)d_out;                  // [64, 32, 16]

    k_zero<<<64, 512>>>();
    k_gen<<<dim3(NI / ITA, NB / 32), 256>>>(x, W);   // votes + pass 0 partials
    k_squash<<<NB, 512>>>(bias, out);
    k_pass<<<dim3(8, NB), 256>>>();                  // pass 1 partials
    k_squash<<<NB, 512>>>(bias, out);
    k_pass<<<dim3(8, NB), 256>>>();                  // pass 2 partials
    k_squash<<<NB, 512>>>(bias, out);
}